// round 13
// baseline (speedup 1.0000x reference)
#include <cuda_runtime.h>
#include <stdint.h>

#define RMS_EPS 1e-6f

// 256-bit global load/store helpers (sm_100+ / Blackwell).
// Loads use the non-coherent/read-only hint (.nc), matching what the
// compiler emits for const __restrict pointers (LDG.E.CONSTANT).
__device__ __forceinline__ void ldg256(const float* p, float v[8]) {
    asm volatile("ld.global.nc.v8.f32 {%0,%1,%2,%3,%4,%5,%6,%7}, [%8];"
        : "=f"(v[0]), "=f"(v[1]), "=f"(v[2]), "=f"(v[3]),
          "=f"(v[4]), "=f"(v[5]), "=f"(v[6]), "=f"(v[7])
        : "l"(p));
}
__device__ __forceinline__ void stg256(float* p, const float v[8]) {
    asm volatile("st.global.v8.f32 [%0], {%1,%2,%3,%4,%5,%6,%7,%8};"
        :: "l"(p),
           "f"(v[0]), "f"(v[1]), "f"(v[2]), "f"(v[3]),
           "f"(v[4]), "f"(v[5]), "f"(v[6]), "f"(v[7])
        : "memory");
}

// Final champion: 512 threads (16 warps), 8 elems/thread, 3x LDG.256 front
// batch (x, residual, weight), two-barrier shuffle reduction, 2x STG.256
// epilogue. 32 regs, 4 CTAs/SM, ~85% DRAM at minimal traffic (16 B/elem).
__global__ void __launch_bounds__(512)
dequant_add_rmsnorm_quant_kernel(const int*   __restrict__ x,
                                 const float* __restrict__ residual,
                                 const float* __restrict__ scale,
                                 const float* __restrict__ weight,
                                 const float* __restrict__ dqs,
                                 float*       __restrict__ out_q,   // output 0 (quantized values as f32)
                                 float*       __restrict__ res_out, // output 1 (res_new as f32)
                                 int H)
{
    const int row = blockIdx.x;
    const int tid = threadIdx.x;
    const size_t base = (size_t)row * (size_t)H;
    const int i0 = tid << 3;  // 8 elements per thread (32B-aligned offsets)

    const float s = __ldg(scale + row) * __ldg(dqs);

    // ---- front-batched 256-bit loads (x, residual, weight) ----
    float xf[8], rf[8], w[8];
    ldg256((const float*)(x + base + i0), xf);   // int32 bits in f32 regs
    ldg256(residual + base + i0, rf);
    ldg256(weight + i0, w);                      // L1/L2-resident after row 0

    float r[8];
    #pragma unroll
    for (int i = 0; i < 8; i++)
        r[i] = fmaf((float)__float_as_int(xf[i]), s, rf[i]);

    float ss = 0.f;
    #pragma unroll
    for (int i = 0; i < 8; i++) ss = fmaf(r[i], r[i], ss);

    // ---- block reduction: 16 warps (proven structure) ----
    #pragma unroll
    for (int o = 16; o > 0; o >>= 1)
        ss += __shfl_xor_sync(0xFFFFFFFFu, ss, o);

    __shared__ float wsum[16];
    __shared__ float inv_s;
    const int wid = tid >> 5, lid = tid & 31;
    if (lid == 0) wsum[wid] = ss;
    __syncthreads();
    if (tid < 32) {
        float v = (tid < 16) ? wsum[tid] : 0.f;
        #pragma unroll
        for (int o = 8; o > 0; o >>= 1)
            v += __shfl_xor_sync(0xFFFFFFFFu, v, o);
        if (tid == 0) inv_s = 1.0f / sqrtf(v / (float)H + RMS_EPS);
    }
    __syncthreads();
    const float inv = inv_s;

    // ---- epilogue: quantize, then both 256-bit stores back-to-back ----
    float q[8];
    #pragma unroll
    for (int i = 0; i < 8; i++) {
        float t = rintf(r[i] * inv * w[i]);      // jnp.round = half-to-even
        q[i] = fminf(fmaxf(t, -128.f), 127.f);   // clip; int8 value as f32
    }
    stg256(res_out + base + i0, r);   // res_new (output 1)
    stg256(out_q   + base + i0, q);   // quantized (output 0)
}

extern "C" void kernel_launch(void* const* d_in, const int* in_sizes, int n_in,
                              void* d_out, int out_size)
{
    const int*   x        = (const int*)  d_in[0];
    const float* residual = (const float*)d_in[1];
    const float* scale    = (const float*)d_in[2];
    const float* weight   = (const float*)d_in[3];
    const float* dqs      = (const float*)d_in[4];

    const int T  = in_sizes[2];   // scale is [T]
    const int H  = in_sizes[3];   // weight is [H]

    // Outputs cast to f32 and concatenated: [quant | res_new]
    float* out_q   = (float*)d_out;
    float* res_out = (float*)d_out + (size_t)out_size / 2;

    const int threads = H / 8;   // H=4096 -> 512
    dequant_add_rmsnorm_quant_kernel<<<T, threads>>>(
        x, residual, scale, weight, dqs, out_q, res_out, H);
}

// round 14
// speedup vs baseline: 1.0006x; 1.0006x over previous
#include <cuda_runtime.h>
#include <stdint.h>

#define RMS_EPS 1e-6f

// 256-bit global load/store helpers (sm_100+ / Blackwell).
// Loads are NON-volatile asm: pure reads, so ptxas may reorder/interleave
// them with surrounding math (volatile would act as a scheduling fence).
__device__ __forceinline__ void ldg256(const float* p, float v[8]) {
    asm("ld.global.nc.v8.f32 {%0,%1,%2,%3,%4,%5,%6,%7}, [%8];"
        : "=f"(v[0]), "=f"(v[1]), "=f"(v[2]), "=f"(v[3]),
          "=f"(v[4]), "=f"(v[5]), "=f"(v[6]), "=f"(v[7])
        : "l"(p));
}
__device__ __forceinline__ void stg256(float* p, const float v[8]) {
    asm volatile("st.global.v8.f32 [%0], {%1,%2,%3,%4,%5,%6,%7,%8};"
        :: "l"(p),
           "f"(v[0]), "f"(v[1]), "f"(v[2]), "f"(v[3]),
           "f"(v[4]), "f"(v[5]), "f"(v[6]), "f"(v[7])
        : "memory");
}

// Final champion: 512 threads (16 warps), 8 elems/thread, 3x LDG.256 front
// batch (x, residual, weight), two-barrier shuffle reduction, 2x STG.256
// epilogue. 32 regs, 4 CTAs/SM, ~85% DRAM at minimal traffic (16 B/elem).
__global__ void __launch_bounds__(512)
dequant_add_rmsnorm_quant_kernel(const int*   __restrict__ x,
                                 const float* __restrict__ residual,
                                 const float* __restrict__ scale,
                                 const float* __restrict__ weight,
                                 const float* __restrict__ dqs,
                                 float*       __restrict__ out_q,   // output 0 (quantized values as f32)
                                 float*       __restrict__ res_out, // output 1 (res_new as f32)
                                 int H)
{
    const int row = blockIdx.x;
    const int tid = threadIdx.x;
    const size_t base = (size_t)row * (size_t)H;
    const int i0 = tid << 3;  // 8 elements per thread (32B-aligned offsets)

    const float s = __ldg(scale + row) * __ldg(dqs);

    // ---- front-batched 256-bit loads (x, residual, weight) ----
    float xf[8], rf[8], w[8];
    ldg256((const float*)(x + base + i0), xf);   // int32 bits in f32 regs
    ldg256(residual + base + i0, rf);
    ldg256(weight + i0, w);                      // L1/L2-resident after row 0

    float r[8];
    #pragma unroll
    for (int i = 0; i < 8; i++)
        r[i] = fmaf((float)__float_as_int(xf[i]), s, rf[i]);

    float ss = 0.f;
    #pragma unroll
    for (int i = 0; i < 8; i++) ss = fmaf(r[i], r[i], ss);

    // ---- block reduction: 16 warps (proven structure) ----
    #pragma unroll
    for (int o = 16; o > 0; o >>= 1)
        ss += __shfl_xor_sync(0xFFFFFFFFu, ss, o);

    __shared__ float wsum[16];
    __shared__ float inv_s;
    const int wid = tid >> 5, lid = tid & 31;
    if (lid == 0) wsum[wid] = ss;
    __syncthreads();
    if (tid < 32) {
        float v = (tid < 16) ? wsum[tid] : 0.f;
        #pragma unroll
        for (int o = 8; o > 0; o >>= 1)
            v += __shfl_xor_sync(0xFFFFFFFFu, v, o);
        if (tid == 0) inv_s = 1.0f / sqrtf(v / (float)H + RMS_EPS);
    }
    __syncthreads();
    const float inv = inv_s;

    // ---- epilogue: quantize, then both 256-bit stores back-to-back ----
    float q[8];
    #pragma unroll
    for (int i = 0; i < 8; i++) {
        float t = rintf(r[i] * inv * w[i]);      // jnp.round = half-to-even
        q[i] = fminf(fmaxf(t, -128.f), 127.f);   // clip; int8 value as f32
    }
    stg256(res_out + base + i0, r);   // res_new (output 1)
    stg256(out_q   + base + i0, q);   // quantized (output 0)
}

extern "C" void kernel_launch(void* const* d_in, const int* in_sizes, int n_in,
                              void* d_out, int out_size)
{
    const int*   x        = (const int*)  d_in[0];
    const float* residual = (const float*)d_in[1];
    const float* scale    = (const float*)d_in[2];
    const float* weight   = (const float*)d_in[3];
    const float* dqs      = (const float*)d_in[4];

    const int T  = in_sizes[2];   // scale is [T]
    const int H  = in_sizes[3];   // weight is [H]

    // Outputs cast to f32 and concatenated: [quant | res_new]
    float* out_q   = (float*)d_out;
    float* res_out = (float*)d_out + (size_t)out_size / 2;

    const int threads = H / 8;   // H=4096 -> 512
    dequant_add_rmsnorm_quant_kernel<<<T, threads>>>(
        x, residual, scale, weight, dqs, out_q, res_out, H);
}